// round 10
// baseline (speedup 1.0000x reference)
#include <cuda_runtime.h>

#define BATCH 1024
#define PIX   784

// ---- packed f32x2 helpers (Blackwell FFMA2: only reachable via PTX) --------
typedef unsigned long long u64;
__device__ __forceinline__ u64 pk2(float lo, float hi) {
    u64 r; asm("mov.b64 %0, {%1,%2};" : "=l"(r) : "f"(lo), "f"(hi)); return r;
}
__device__ __forceinline__ void upk2(u64 v, float& lo, float& hi) {
    asm("mov.b64 {%0,%1}, %2;" : "=f"(lo), "=f"(hi) : "l"(v));
}
__device__ __forceinline__ u64 fma2(u64 a, u64 b, u64 c) {
    u64 d; asm("fma.rn.f32x2 %0, %1, %2, %3;" : "=l"(d) : "l"(a), "l"(b), "l"(c));
    return d;
}

// ---------------------------------------------------------------------------
// ONE kernel per sample block: feat + conv + fc1 + fc2, nothing to DRAM but
// the 10 outputs.
//  (a) persistence landscape: tent(v)=max(0,min(t-v,death-t)) non-increasing
//      in v -> top-2 at every t = tents of two SMALLEST v -> (min1,min2,max)
//      + 64 closed-form evals + 64x64 matvec, straight into zs[784..847].
//  (b) conv(1->32)->relu->conv(32->1)->relu with channel-pair f32x2 packing
//      (FFMA2, weight pairs via LDS.64); outputs straight into zs[0..783].
//  (c) fc1: 848x64 GEMV, 7 warps k-slice, thread owns adjacent f-pair ->
//      coalesced LDG.64 of L2-resident fc1_w + 1 FFMA2/k. Overlaps across
//      blocks with (b)'s fma work (different pipes).
//  (d) fc2: 64x10 head.
// ---------------------------------------------------------------------------
__global__ void __launch_bounds__(224) fused_kernel(
    const float* __restrict__ x,
    const float* __restrict__ w1, const float* __restrict__ b1,
    const float* __restrict__ w2, const float* __restrict__ b2,
    const float* __restrict__ v005, const float* __restrict__ v02,
    const float* __restrict__ g1w, const float* __restrict__ g1b,
    const float* __restrict__ g2w, const float* __restrict__ g2b,
    const float* __restrict__ fc1w, const float* __restrict__ fc1b,
    const float* __restrict__ fc2w, const float* __restrict__ fc2b,
    float* __restrict__ out)
{
    __shared__ __align__(16) float  xs[30][32];       // input with zero halo
    __shared__ __align__(16) float2 mids2[4][30][32]; // cpair group, zero halo
    __shared__ __align__(16) float  w1s[288];         // [tap][32 ch]
    __shared__ __align__(16) float  w2s[288];
    __shared__ __align__(16) float  b1s[32];
    __shared__ float b2s;
    __shared__ float red1[7], red2[7], redm[7];
    __shared__ float stats[2][3];
    __shared__ float xls[2][64];
    __shared__ __align__(16) float zs[852];           // [hconv 784 | feat 64]
    __shared__ __align__(16) float ph[7][64];         // fc1 k-slice partials
    __shared__ float hs[64];

    const int tid  = threadIdx.x;
    const int lane = tid & 31, wid = tid >> 5;
    const int b    = blockIdx.x;

    // ---- feat part 1: (min1, min2, max) reduction per branch ----
    #pragma unroll
    for (int br = 0; br < 2; br++) {
        const float4* v = (const float4*)((br ? v02 : v005) + b * PIX);
        float m1 = 1e30f, m2 = 1e30f, mx = -1e30f;
        if (tid < 196) {
            const float4 q = v[tid];
            float hv;
            mx = fmaxf(fmaxf(q.x, q.y), fmaxf(q.z, q.w));
            m1 = fminf(q.x, q.y); m2 = fmaxf(q.x, q.y);
            hv = fmaxf(m1, q.z); m1 = fminf(m1, q.z); m2 = fminf(m2, hv);
            hv = fmaxf(m1, q.w); m1 = fminf(m1, q.w); m2 = fminf(m2, hv);
        }
        #pragma unroll
        for (int o = 16; o; o >>= 1) {
            const float o1 = __shfl_xor_sync(0xFFFFFFFFu, m1, o);
            const float o2 = __shfl_xor_sync(0xFFFFFFFFu, m2, o);
            const float om = __shfl_xor_sync(0xFFFFFFFFu, mx, o);
            const float hi = fmaxf(m1, o1);
            m1 = fminf(m1, o1);
            m2 = fminf(hi, fminf(m2, o2));
            mx = fmaxf(mx, om);
        }
        if (lane == 0) { red1[wid] = m1; red2[wid] = m2; redm[wid] = mx; }
        __syncthreads();
        if (tid == 0) {
            float a1 = red1[0], a2 = red2[0], am = redm[0];
            #pragma unroll
            for (int w = 1; w < 7; w++) {
                const float o1 = red1[w], o2 = red2[w];
                const float hi = fmaxf(a1, o1);
                a1 = fminf(a1, o1);
                a2 = fminf(hi, fminf(a2, o2));
                am = fmaxf(am, redm[w]);
            }
            stats[br][0] = a1; stats[br][1] = a2; stats[br][2] = am;
        }
        __syncthreads();
    }
    // 64 landscape values per branch: xls[br][k*32 + t]
    if (tid < 128) {
        const int br = tid >> 6, i = tid & 63;
        const int k = i >> 5, t = i & 31;
        const float t0 = br ? 0.05f : 0.01f;
        const float dt = br ? (0.25f / 31.0f) : (0.28f / 31.0f);
        const float tv = t0 + (float)t * dt;
        xls[br][i] = fmaxf(0.f, fminf(tv - stats[br][k], stats[br][2] - tv));
    }

    // ---- conv smem init ----
    for (int i = tid; i < 30 * 32; i += 224) (&xs[0][0])[i] = 0.f;
    for (int i = tid; i < 4 * 30 * 32; i += 224)
        (&mids2[0][0][0])[i] = make_float2(0.f, 0.f);
    for (int i = tid; i < 288; i += 224) { w1s[i] = w1[i]; w2s[i] = w2[i]; }
    if (tid < 32) b1s[tid] = b1[tid];
    if (tid == 0) b2s = b2[0];
    __syncthreads();

    // input load: 28 % 4 == 0 so float4 never crosses a row
    if (tid < 196) {
        const float4 q = ((const float4*)(x + b * PIX))[tid];
        const int r = tid / 7, c = (tid % 7) * 4;
        xs[r + 1][c + 1] = q.x; xs[r + 1][c + 2] = q.y;
        xs[r + 1][c + 3] = q.z; xs[r + 1][c + 4] = q.w;
    }
    __syncthreads();

    const bool active = tid < 196;
    const int xcol = tid % 28;
    const int y0   = (tid / 28) * 4;

    u64 xp[6][3];   // (x,x) packs, reused across all 16 channel pairs
    if (active) {
        #pragma unroll
        for (int rr = 0; rr < 6; rr++)
            #pragma unroll
            for (int dx = 0; dx < 3; dx++) {
                const float xv = xs[y0 + rr][xcol + dx];
                xp[rr][dx] = pk2(xv, xv);
            }
    }
    u64 a0 = 0, a1 = 0, a2 = 0, a3 = 0;   // packed-over-channel accumulators

    for (int g = 0; g < 4; g++) {
        if (active) {
            #pragma unroll
            for (int cp = 0; cp < 4; cp++) {
                const int c2 = (g * 4 + cp) * 2;      // even channel index
                const u64 bv = *(const u64*)&b1s[c2];
                u64 m0 = bv, m1 = bv, m2 = bv, m3 = bv;
                #pragma unroll
                for (int dy = 0; dy < 3; dy++)
                    #pragma unroll
                    for (int dx = 0; dx < 3; dx++) {
                        const u64 wv = *(const u64*)&w1s[(dy * 3 + dx) * 32 + c2];
                        m0 = fma2(xp[0 + dy][dx], wv, m0);
                        m1 = fma2(xp[1 + dy][dx], wv, m1);
                        m2 = fma2(xp[2 + dy][dx], wv, m2);
                        m3 = fma2(xp[3 + dy][dx], wv, m3);
                    }
                float lo, hi;
                upk2(m0, lo, hi);
                mids2[cp][y0 + 1][xcol + 1] = make_float2(fmaxf(lo, 0.f), fmaxf(hi, 0.f));
                upk2(m1, lo, hi);
                mids2[cp][y0 + 2][xcol + 1] = make_float2(fmaxf(lo, 0.f), fmaxf(hi, 0.f));
                upk2(m2, lo, hi);
                mids2[cp][y0 + 3][xcol + 1] = make_float2(fmaxf(lo, 0.f), fmaxf(hi, 0.f));
                upk2(m3, lo, hi);
                mids2[cp][y0 + 4][xcol + 1] = make_float2(fmaxf(lo, 0.f), fmaxf(hi, 0.f));
            }
        }
        __syncthreads();
        if (active) {
            #pragma unroll
            for (int cp = 0; cp < 4; cp++) {
                const int c2 = (g * 4 + cp) * 2;
                #pragma unroll
                for (int dx = 0; dx < 3; dx++) {
                    u64 c[6];
                    #pragma unroll
                    for (int rr = 0; rr < 6; rr++)
                        c[rr] = *(const u64*)&mids2[cp][y0 + rr][xcol + dx];
                    #pragma unroll
                    for (int dy = 0; dy < 3; dy++) {
                        const u64 wv = *(const u64*)&w2s[(dy * 3 + dx) * 32 + c2];
                        a0 = fma2(c[0 + dy], wv, a0);
                        a1 = fma2(c[1 + dy], wv, a1);
                        a2 = fma2(c[2 + dy], wv, a2);
                        a3 = fma2(c[3 + dy], wv, a3);
                    }
                }
            }
        }
        __syncthreads();
    }
    // conv epilogue -> zs[0..783] (smem only, no DRAM)
    if (active) {
        const float bb = b2s;
        float lo, hi;
        float* zo = zs + y0 * 28 + xcol;
        upk2(a0, lo, hi); zo[0]  = fmaxf(lo + hi + bb, 0.f);
        upk2(a1, lo, hi); zo[28] = fmaxf(lo + hi + bb, 0.f);
        upk2(a2, lo, hi); zo[56] = fmaxf(lo + hi + bb, 0.f);
        upk2(a3, lo, hi); zo[84] = fmaxf(lo + hi + bb, 0.f);
    }

    // ---- feat part 2: relu(xls @ g_w + g_b) -> zs[784..847] ----
    if (tid < 64) {
        const int br = tid >> 5, f = tid & 31;
        const float* gw = br ? g2w : g1w;
        float a = (br ? g2b : g1b)[f];
        #pragma unroll 8
        for (int i = 0; i < 64; i++) a += xls[br][i] * gw[i * 32 + f];
        zs[784 + br * 32 + f] = fmaxf(a, 0.f);
    }
    __syncthreads();

    // ---- fc1: 848x64 GEMV. warp = k-slice (7x~121), lane = adjacent f-pair.
    // fc1_w rows stream from L2 (resident across all 1024 blocks).
    {
        const int k0 = wid * 121;
        const int k1 = (wid == 6) ? 848 : k0 + 121;
        u64 acc = 0;
        const float* wp = fc1w + lane * 2;
        #pragma unroll 4
        for (int k = k0; k < k1; k++) {
            const float z = zs[k];                        // warp-broadcast LDS
            const u64 wv = *(const u64*)(wp + k * 64);    // coalesced LDG.64
            acc = fma2(pk2(z, z), wv, acc);
        }
        float lo, hi; upk2(acc, lo, hi);
        ph[wid][lane * 2] = lo; ph[wid][lane * 2 + 1] = hi;
    }
    __syncthreads();
    if (tid < 64) {
        float h = fc1b[tid];
        #pragma unroll
        for (int w = 0; w < 7; w++) h += ph[w][tid];
        hs[tid] = fmaxf(h, 0.f);
    }
    __syncthreads();
    // ---- fc2: 64 -> 10 head ----
    if (tid < 10) {
        float a = fc2b[tid];
        #pragma unroll
        for (int f = 0; f < 64; f++) a += hs[f] * fc2w[f * 10 + tid];
        out[b * 10 + tid] = a;
    }
}

// ---------------------------------------------------------------------------
extern "C" void kernel_launch(void* const* d_in, const int* in_sizes, int n_in,
                              void* d_out, int out_size)
{
    const float* x       = (const float*)d_in[0];
    const float* xd005   = (const float*)d_in[1];
    const float* xd02    = (const float*)d_in[2];
    const float* conv_w1 = (const float*)d_in[3];
    const float* conv_b1 = (const float*)d_in[4];
    const float* conv_w2 = (const float*)d_in[5];
    const float* conv_b2 = (const float*)d_in[6];
    const float* g1w     = (const float*)d_in[7];
    const float* g1b     = (const float*)d_in[8];
    const float* g2w     = (const float*)d_in[9];
    const float* g2b     = (const float*)d_in[10];
    const float* fc1w    = (const float*)d_in[11];
    const float* fc1b    = (const float*)d_in[12];
    const float* fc2w    = (const float*)d_in[13];
    const float* fc2b    = (const float*)d_in[14];
    float* out = (float*)d_out;

    fused_kernel<<<BATCH, 224>>>(x, conv_w1, conv_b1, conv_w2, conv_b2,
                                 xd005, xd02, g1w, g1b, g2w, g2b,
                                 fc1w, fc1b, fc2w, fc2b, out);
}

// round 15
// speedup vs baseline: 1.0047x; 1.0047x over previous
#include <cuda_runtime.h>

#define BATCH 1024
#define PIX   784

// ---- packed f32x2 helpers (Blackwell FFMA2: only reachable via PTX) --------
typedef unsigned long long u64;
__device__ __forceinline__ u64 pk2(float lo, float hi) {
    u64 r; asm("mov.b64 %0, {%1,%2};" : "=l"(r) : "f"(lo), "f"(hi)); return r;
}
__device__ __forceinline__ void upk2(u64 v, float& lo, float& hi) {
    asm("mov.b64 {%0,%1}, %2;" : "=f"(lo), "=f"(hi) : "l"(v));
}
__device__ __forceinline__ u64 fma2(u64 a, u64 b, u64 c) {
    u64 d; asm("fma.rn.f32x2 %0, %1, %2, %3;" : "=l"(d) : "l"(a), "l"(b), "l"(c));
    return d;
}

// ---------------------------------------------------------------------------
// ONE kernel, one block per sample: feat + conv + fc1 + fc2; only the 10
// outputs touch DRAM. Register-pressure round: xp repacked per g-iteration
// (dead across conv2) + __launch_bounds__(224,4) -> 4 CTAs/SM (was 3).
// ---------------------------------------------------------------------------
__global__ void __launch_bounds__(224, 4) fused_kernel(
    const float* __restrict__ x,
    const float* __restrict__ w1, const float* __restrict__ b1,
    const float* __restrict__ w2, const float* __restrict__ b2,
    const float* __restrict__ v005, const float* __restrict__ v02,
    const float* __restrict__ g1w, const float* __restrict__ g1b,
    const float* __restrict__ g2w, const float* __restrict__ g2b,
    const float* __restrict__ fc1w, const float* __restrict__ fc1b,
    const float* __restrict__ fc2w, const float* __restrict__ fc2b,
    float* __restrict__ out)
{
    __shared__ __align__(16) float  xs[30][32];       // input with zero halo
    __shared__ __align__(16) float2 mids2[4][30][32]; // cpair group, zero halo
    __shared__ __align__(16) float  w1s[288];         // [tap][32 ch]
    __shared__ __align__(16) float  w2s[288];
    __shared__ __align__(16) float  b1s[32];
    __shared__ float b2s;
    __shared__ float red1[2][7], red2[2][7], redm[2][7];
    __shared__ float stats[2][3];
    __shared__ float xls[2][64];
    __shared__ __align__(16) float zs[852];           // [hconv 784 | feat 64]
    __shared__ __align__(16) float ph[7][64];         // fc1 k-slice partials
    __shared__ float hs[64];

    const int tid  = threadIdx.x;
    const int lane = tid & 31, wid = tid >> 5;
    const int b    = blockIdx.x;

    // ---- feat part 1: (min1, min2, max) per branch; 2 barriers total ----
    #pragma unroll
    for (int br = 0; br < 2; br++) {
        const float4* v = (const float4*)((br ? v02 : v005) + b * PIX);
        float m1 = 1e30f, m2 = 1e30f, mx = -1e30f;
        if (tid < 196) {
            const float4 q = v[tid];
            float hv;
            mx = fmaxf(fmaxf(q.x, q.y), fmaxf(q.z, q.w));
            m1 = fminf(q.x, q.y); m2 = fmaxf(q.x, q.y);
            hv = fmaxf(m1, q.z); m1 = fminf(m1, q.z); m2 = fminf(m2, hv);
            hv = fmaxf(m1, q.w); m1 = fminf(m1, q.w); m2 = fminf(m2, hv);
        }
        #pragma unroll
        for (int o = 16; o; o >>= 1) {
            const float o1 = __shfl_xor_sync(0xFFFFFFFFu, m1, o);
            const float o2 = __shfl_xor_sync(0xFFFFFFFFu, m2, o);
            const float om = __shfl_xor_sync(0xFFFFFFFFu, mx, o);
            const float hi = fmaxf(m1, o1);
            m1 = fminf(m1, o1);
            m2 = fminf(hi, fminf(m2, o2));
            mx = fmaxf(mx, om);
        }
        if (lane == 0) { red1[br][wid] = m1; red2[br][wid] = m2; redm[br][wid] = mx; }
    }
    __syncthreads();
    if (tid < 2) {                     // one thread per branch, in parallel
        const int br = tid;
        float a1 = red1[br][0], a2 = red2[br][0], am = redm[br][0];
        #pragma unroll
        for (int w = 1; w < 7; w++) {
            const float o1 = red1[br][w], o2 = red2[br][w];
            const float hi = fmaxf(a1, o1);
            a1 = fminf(a1, o1);
            a2 = fminf(hi, fminf(a2, o2));
            am = fmaxf(am, redm[br][w]);
        }
        stats[br][0] = a1; stats[br][1] = a2; stats[br][2] = am;
    }

    // ---- conv smem init (overlaps the stats barrier) ----
    for (int i = tid; i < 30 * 32; i += 224) (&xs[0][0])[i] = 0.f;
    for (int i = tid; i < 4 * 30 * 32; i += 224)
        (&mids2[0][0][0])[i] = make_float2(0.f, 0.f);
    for (int i = tid; i < 288; i += 224) { w1s[i] = w1[i]; w2s[i] = w2[i]; }
    if (tid < 32) b1s[tid] = b1[tid];
    if (tid == 0) b2s = b2[0];
    __syncthreads();

    // 64 landscape values per branch: xls[br][k*32 + t]
    if (tid < 128) {
        const int br = tid >> 6, i = tid & 63;
        const int k = i >> 5, t = i & 31;
        const float t0 = br ? 0.05f : 0.01f;
        const float dt = br ? (0.25f / 31.0f) : (0.28f / 31.0f);
        const float tv = t0 + (float)t * dt;
        xls[br][i] = fmaxf(0.f, fminf(tv - stats[br][k], stats[br][2] - tv));
    }
    // input load: 28 % 4 == 0 so float4 never crosses a row
    if (tid < 196) {
        const float4 q = ((const float4*)(x + b * PIX))[tid];
        const int r = tid / 7, c = (tid % 7) * 4;
        xs[r + 1][c + 1] = q.x; xs[r + 1][c + 2] = q.y;
        xs[r + 1][c + 3] = q.z; xs[r + 1][c + 4] = q.w;
    }
    __syncthreads();

    const bool active = tid < 196;
    const int xcol = tid % 28;
    const int y0   = (tid / 28) * 4;

    u64 a0 = 0, a1 = 0, a2 = 0, a3 = 0;   // packed-over-channel accumulators

    for (int g = 0; g < 4; g++) {
        if (active) {
            // repack conv1 inputs HERE: live only through conv1 of this g
            // (frees ~36 regs during conv2 -> 4 CTAs/SM fit)
            u64 xp[6][3];
            #pragma unroll
            for (int rr = 0; rr < 6; rr++)
                #pragma unroll
                for (int dx = 0; dx < 3; dx++) {
                    const float xv = xs[y0 + rr][xcol + dx];
                    xp[rr][dx] = pk2(xv, xv);
                }
            #pragma unroll
            for (int cp = 0; cp < 4; cp++) {
                const int c2 = (g * 4 + cp) * 2;      // even channel index
                const u64 bv = *(const u64*)&b1s[c2];
                u64 m0 = bv, m1 = bv, m2 = bv, m3 = bv;
                #pragma unroll
                for (int dy = 0; dy < 3; dy++)
                    #pragma unroll
                    for (int dx = 0; dx < 3; dx++) {
                        const u64 wv = *(const u64*)&w1s[(dy * 3 + dx) * 32 + c2];
                        m0 = fma2(xp[0 + dy][dx], wv, m0);
                        m1 = fma2(xp[1 + dy][dx], wv, m1);
                        m2 = fma2(xp[2 + dy][dx], wv, m2);
                        m3 = fma2(xp[3 + dy][dx], wv, m3);
                    }
                float lo, hi;
                upk2(m0, lo, hi);
                mids2[cp][y0 + 1][xcol + 1] = make_float2(fmaxf(lo, 0.f), fmaxf(hi, 0.f));
                upk2(m1, lo, hi);
                mids2[cp][y0 + 2][xcol + 1] = make_float2(fmaxf(lo, 0.f), fmaxf(hi, 0.f));
                upk2(m2, lo, hi);
                mids2[cp][y0 + 3][xcol + 1] = make_float2(fmaxf(lo, 0.f), fmaxf(hi, 0.f));
                upk2(m3, lo, hi);
                mids2[cp][y0 + 4][xcol + 1] = make_float2(fmaxf(lo, 0.f), fmaxf(hi, 0.f));
            }
        }
        __syncthreads();
        if (active) {
            #pragma unroll
            for (int cp = 0; cp < 4; cp++) {
                const int c2 = (g * 4 + cp) * 2;
                #pragma unroll
                for (int dx = 0; dx < 3; dx++) {
                    u64 c[6];
                    #pragma unroll
                    for (int rr = 0; rr < 6; rr++)
                        c[rr] = *(const u64*)&mids2[cp][y0 + rr][xcol + dx];
                    #pragma unroll
                    for (int dy = 0; dy < 3; dy++) {
                        const u64 wv = *(const u64*)&w2s[(dy * 3 + dx) * 32 + c2];
                        a0 = fma2(c[0 + dy], wv, a0);
                        a1 = fma2(c[1 + dy], wv, a1);
                        a2 = fma2(c[2 + dy], wv, a2);
                        a3 = fma2(c[3 + dy], wv, a3);
                    }
                }
            }
        }
        __syncthreads();
    }
    // conv epilogue -> zs[0..783] (smem only, no DRAM)
    if (active) {
        const float bb = b2s;
        float lo, hi;
        float* zo = zs + y0 * 28 + xcol;
        upk2(a0, lo, hi); zo[0]  = fmaxf(lo + hi + bb, 0.f);
        upk2(a1, lo, hi); zo[28] = fmaxf(lo + hi + bb, 0.f);
        upk2(a2, lo, hi); zo[56] = fmaxf(lo + hi + bb, 0.f);
        upk2(a3, lo, hi); zo[84] = fmaxf(lo + hi + bb, 0.f);
    }

    // ---- feat part 2: relu(xls @ g_w + g_b) -> zs[784..847] ----
    if (tid < 64) {
        const int br = tid >> 5, f = tid & 31;
        const float* gw = br ? g2w : g1w;
        float a = (br ? g2b : g1b)[f];
        #pragma unroll 8
        for (int i = 0; i < 64; i++) a += xls[br][i] * gw[i * 32 + f];
        zs[784 + br * 32 + f] = fmaxf(a, 0.f);
    }
    __syncthreads();

    // ---- fc1: 848x64 GEMV. warp = k-slice (7x~121), lane = adjacent f-pair.
    // fc1_w rows stream from L2 (resident across all 1024 blocks).
    {
        const int k0 = wid * 121;
        const int k1 = (wid == 6) ? 848 : k0 + 121;
        u64 acc = 0;
        const float* wp = fc1w + lane * 2;
        #pragma unroll 4
        for (int k = k0; k < k1; k++) {
            const float z = zs[k];                        // warp-broadcast LDS
            const u64 wv = *(const u64*)(wp + k * 64);    // coalesced LDG.64
            acc = fma2(pk2(z, z), wv, acc);
        }
        float lo, hi; upk2(acc, lo, hi);
        ph[wid][lane * 2] = lo; ph[wid][lane * 2 + 1] = hi;
    }
    __syncthreads();
    if (tid < 64) {
        float h = fc1b[tid];
        #pragma unroll
        for (int w = 0; w < 7; w++) h += ph[w][tid];
        hs[tid] = fmaxf(h, 0.f);
    }
    __syncthreads();
    // ---- fc2: 64 -> 10 head ----
    if (tid < 10) {
        float a = fc2b[tid];
        #pragma unroll
        for (int f = 0; f < 64; f++) a += hs[f] * fc2w[f * 10 + tid];
        out[b * 10 + tid] = a;
    }
}

// ---------------------------------------------------------------------------
extern "C" void kernel_launch(void* const* d_in, const int* in_sizes, int n_in,
                              void* d_out, int out_size)
{
    const float* x       = (const float*)d_in[0];
    const float* xd005   = (const float*)d_in[1];
    const float* xd02    = (const float*)d_in[2];
    const float* conv_w1 = (const float*)d_in[3];
    const float* conv_b1 = (const float*)d_in[4];
    const float* conv_w2 = (const float*)d_in[5];
    const float* conv_b2 = (const float*)d_in[6];
    const float* g1w     = (const float*)d_in[7];
    const float* g1b     = (const float*)d_in[8];
    const float* g2w     = (const float*)d_in[9];
    const float* g2b     = (const float*)d_in[10];
    const float* fc1w    = (const float*)d_in[11];
    const float* fc1b    = (const float*)d_in[12];
    const float* fc2w    = (const float*)d_in[13];
    const float* fc2b    = (const float*)d_in[14];
    float* out = (float*)d_out;

    fused_kernel<<<BATCH, 224>>>(x, conv_w1, conv_b1, conv_w2, conv_b2,
                                 xd005, xd02, g1w, g1b, g2w, g2b,
                                 fc1w, fc1b, fc2w, fc2b, out);
}